// round 2
// baseline (speedup 1.0000x reference)
#include <cuda_runtime.h>
#include <cuda_bf16.h>

// ---------------------------------------------------------------------------
// HypernymVisual: h = relu(vfs)@W1 + b1 ; e = relu(h)@W2 + b2 ;
// scores[n,l] = -sqrt(sum_d relu(lv[l,d] - e[n,d])^2)
//
// Round 2: packed f32x2 math; packed ReLU done as signed-int32 max per lane
// (bit-exact with fmaxf(x,0)) — IMNMX rides the alu pipe under the fma pipe.
// ---------------------------------------------------------------------------

#define NV   256
#define DV   4096
#define DH   1024
#define DE   100
#define LL   20000

typedef unsigned long long u64;

// scratch (device globals: allowed; no runtime alloc)
__device__ float g_hp[2][NV * DH];       // gemm1 K-split partials (no bias)
__device__ float g_ep[8][NV * DE];       // gemm2 K-split partials (no bias)

// ---- f32x2 helpers (packed two-lane fp32) ---------------------------------
__device__ __forceinline__ u64 f2add(u64 a, u64 b) {
    u64 r; asm("add.rn.f32x2 %0,%1,%2;" : "=l"(r) : "l"(a), "l"(b)); return r;
}
__device__ __forceinline__ u64 f2fma(u64 a, u64 b, u64 c) {
    u64 r; asm("fma.rn.f32x2 %0,%1,%2,%3;" : "=l"(r) : "l"(a), "l"(b), "l"(c)); return r;
}
// packed ReLU: per-lane fmaxf(x,0) == signed int32 max(x,0) bitwise (IEEE754).
__device__ __forceinline__ u64 f2relu(u64 x) {
    u64 r;
    asm("{\n\t"
        ".reg .s32 lo, hi;\n\t"
        "mov.b64 {lo, hi}, %1;\n\t"
        "max.s32 lo, lo, 0;\n\t"
        "max.s32 hi, hi, 0;\n\t"
        "mov.b64 %0, {lo, hi};\n\t"
        "}" : "=l"(r) : "l"(x));
    return r;
}
__device__ __forceinline__ u64 fpack(float x, float y) {
    u64 r;
    unsigned lo = __float_as_uint(x), hi = __float_as_uint(y);
    asm("mov.b64 %0,{%1,%2};" : "=l"(r) : "r"(lo), "r"(hi));
    return r;
}
__device__ __forceinline__ float2 funpack(u64 a) {
    unsigned lo, hi;
    asm("mov.b64 {%0,%1},%2;" : "=r"(lo), "=r"(hi) : "l"(a));
    return make_float2(__uint_as_float(lo), __uint_as_float(hi));
}
__device__ __forceinline__ float fsqrt_ap(float x) {
    float r; asm("sqrt.approx.f32 %0,%1;" : "=f"(r) : "f"(x)); return r;
}

// ---------------------------------------------------------------------------
// GEMM1: g_hp[z] = relu(vfs) @ W1   (K-split z in {0,1}, K half = 2048)
// block: 64(m) x 64(n) tile, 256 threads, thread tile 4m x 4n via f32x2 pairs
// grid: (16 n-tiles, 4 m-tiles, 2 k-splits) = 128 blocks
// ---------------------------------------------------------------------------
__global__ __launch_bounds__(256) void gemm1_kernel(
    const float* __restrict__ vfs, const float* __restrict__ W1)
{
    __shared__ __align__(16) float As[16][68];   // transposed: As[k][m]
    __shared__ __align__(16) float Bs[16][68];   // Bs[k][n]

    const int t  = threadIdx.x;
    const int m0 = blockIdx.y * 64;
    const int n0 = blockIdx.x * 64;
    const int kb0 = blockIdx.z * 2048;

    const int tx = t & 15;        // n-group
    const int ty = t >> 4;        // m-group
    const int am = t >> 2, ac = t & 3;     // A load mapping
    const int bk = t >> 4, bn4 = t & 15;   // B load mapping

    u64 acc[2][4];
#pragma unroll
    for (int i = 0; i < 2; ++i)
#pragma unroll
        for (int j = 0; j < 4; ++j) acc[i][j] = 0ull;

    const float4* aG = (const float4*)(vfs + (size_t)(m0 + am) * DV);

    for (int kt = 0; kt < 128; ++kt) {
        const int kb = kb0 + kt * 16;

        // load A tile (64m x 16k), relu at load, store transposed
        float4 av = aG[(kb >> 2) + ac];
        av.x = fmaxf(av.x, 0.f); av.y = fmaxf(av.y, 0.f);
        av.z = fmaxf(av.z, 0.f); av.w = fmaxf(av.w, 0.f);
        As[ac * 4 + 0][am] = av.x;
        As[ac * 4 + 1][am] = av.y;
        As[ac * 4 + 2][am] = av.z;
        As[ac * 4 + 3][am] = av.w;

        // load B tile (16k x 64n)
        float4 wv = *(const float4*)(W1 + (size_t)(kb + bk) * DH + n0 + bn4 * 4);
        *(float4*)&Bs[bk][bn4 * 4] = wv;

        __syncthreads();

#pragma unroll
        for (int kk = 0; kk < 16; ++kk) {
            ulonglong2 ap = *(const ulonglong2*)&As[kk][ty * 4];   // 2 m-pairs
            float4 b4 = *(const float4*)&Bs[kk][tx * 4];
            u64 bd0 = fpack(b4.x, b4.x);
            u64 bd1 = fpack(b4.y, b4.y);
            u64 bd2 = fpack(b4.z, b4.z);
            u64 bd3 = fpack(b4.w, b4.w);
            acc[0][0] = f2fma(ap.x, bd0, acc[0][0]);
            acc[0][1] = f2fma(ap.x, bd1, acc[0][1]);
            acc[0][2] = f2fma(ap.x, bd2, acc[0][2]);
            acc[0][3] = f2fma(ap.x, bd3, acc[0][3]);
            acc[1][0] = f2fma(ap.y, bd0, acc[1][0]);
            acc[1][1] = f2fma(ap.y, bd1, acc[1][1]);
            acc[1][2] = f2fma(ap.y, bd2, acc[1][2]);
            acc[1][3] = f2fma(ap.y, bd3, acc[1][3]);
        }
        __syncthreads();
    }

    float* outp = g_hp[blockIdx.z];
#pragma unroll
    for (int i = 0; i < 2; ++i)
#pragma unroll
        for (int j = 0; j < 4; ++j) {
            float2 v = funpack(acc[i][j]);
            int m = m0 + ty * 4 + i * 2;
            int n = n0 + tx * 4 + j;
            outp[(size_t)m * DH + n]       = v.x;
            outp[(size_t)(m + 1) * DH + n] = v.y;
        }
}

// ---------------------------------------------------------------------------
// GEMM2: g_ep[s] = relu(g_hp[0]+g_hp[1]+b1) @ W2  over k-range of split s
// block: 16 m-rows, all 100 j, 128-wide k split; grid (16, 8) = 128 blocks
// ---------------------------------------------------------------------------
__global__ __launch_bounds__(256) void gemm2_kernel(
    const float* __restrict__ W2, const float* __restrict__ b1)
{
    __shared__ __align__(16) float sh_h[16 * 64];
    __shared__ float sh_w[64 * 112];   // padded rows; pad region unused garbage

    const int t = threadIdx.x;
    const int m0  = blockIdx.x * 16;
    const int ks0 = blockIdx.y * 128;
    const int tm = t >> 4, tj = t & 15;

    float acc[7];
#pragma unroll
    for (int u = 0; u < 7; ++u) acc[u] = 0.f;

    for (int c = 0; c < 2; ++c) {
        const int kc = ks0 + c * 64;

        // load & fuse h = relu(p0+p1+b1): 16x64 floats, 4 per thread
        {
            int idx = t * 4;
            int m = idx >> 6, kk = idx & 63;
            float4 h0 = *(const float4*)(g_hp[0] + (size_t)(m0 + m) * DH + kc + kk);
            float4 h1 = *(const float4*)(g_hp[1] + (size_t)(m0 + m) * DH + kc + kk);
            float4 bb = *(const float4*)(b1 + kc + kk);
            float4 hv;
            hv.x = fmaxf(h0.x + h1.x + bb.x, 0.f);
            hv.y = fmaxf(h0.y + h1.y + bb.y, 0.f);
            hv.z = fmaxf(h0.z + h1.z + bb.z, 0.f);
            hv.w = fmaxf(h0.w + h1.w + bb.w, 0.f);
            *(float4*)&sh_h[m * 64 + kk] = hv;
        }
        // load W2 chunk (64 x 100)
#pragma unroll
        for (int r = 0; r < 25; ++r) {
            int idx = r * 256 + t;
            int kk = idx / 100;
            int j  = idx - kk * 100;
            sh_w[kk * 112 + j] = W2[(size_t)(kc + kk) * DE + j];
        }
        __syncthreads();

#pragma unroll 8
        for (int kk = 0; kk < 64; ++kk) {
            float a = sh_h[tm * 64 + kk];
#pragma unroll
            for (int u = 0; u < 7; ++u)
                acc[u] += a * sh_w[kk * 112 + tj + 16 * u];
        }
        __syncthreads();
    }

    float* ep = g_ep[blockIdx.y];
#pragma unroll
    for (int u = 0; u < 7; ++u) {
        int j = tj + 16 * u;
        if (j < DE) ep[(size_t)(m0 + tm) * DE + j] = acc[u];
    }
}

// ---------------------------------------------------------------------------
// Scoring: out[n,l] = -sqrt( sum_d relu(lv[l,d] - e[n,d])^2 )
// e tile (16 n rows) in smem, NEGATED with b2 folded in.
// 256 threads; each thread: 2 l's x 16 n's, f32x2 accumulation along d.
// grid: (ceil(20000/512)=40, 16 n-tiles) = 640 blocks
// ---------------------------------------------------------------------------
__global__ __launch_bounds__(256, 2) void score_kernel(
    const float* __restrict__ lv, const float* __restrict__ b2,
    float* __restrict__ out)
{
    __shared__ __align__(16) float e_s[16 * DE];

    const int t  = threadIdx.x;
    const int n0 = blockIdx.y * 16;

    // build negated e tile: e_s[n][d] = -(b2[d] + sum_s g_ep[s][n0+n][d])
    for (int idx = t; idx < 16 * DE; idx += 256) {
        int n = idx / DE;
        int d = idx - n * DE;
        float v = b2[d];
#pragma unroll
        for (int s = 0; s < 8; ++s) v += g_ep[s][(size_t)(n0 + n) * DE + d];
        e_s[idx] = -v;
    }
    __syncthreads();

    const u64* es2 = (const u64*)e_s;   // 50 d-pairs per n row

    const int l0 = blockIdx.x * 512 + t;
    const int l1 = l0 + 256;
    const int lc0 = min(l0, LL - 1);
    const int lc1 = min(l1, LL - 1);

    const ulonglong2* p0 = (const ulonglong2*)(lv + (size_t)lc0 * DE);
    const ulonglong2* p1 = (const ulonglong2*)(lv + (size_t)lc1 * DE);

    u64 acc0[16], acc1[16];
#pragma unroll
    for (int n = 0; n < 16; ++n) { acc0[n] = 0ull; acc1[n] = 0ull; }

    ulonglong2 a0 = p0[0], a1 = p1[0];

    for (int q = 0; q < 25; ++q) {
        const int qn = (q < 24) ? (q + 1) : 24;
        ulonglong2 na0 = p0[qn];
        ulonglong2 na1 = p1[qn];

        const int dp = q << 1;
#pragma unroll
        for (int n = 0; n < 16; ++n) {
            u64 e2 = es2[n * 50 + dp];
            u64 t0 = f2relu(f2add(a0.x, e2));
            acc0[n] = f2fma(t0, t0, acc0[n]);
            u64 t1 = f2relu(f2add(a1.x, e2));
            acc1[n] = f2fma(t1, t1, acc1[n]);
        }
#pragma unroll
        for (int n = 0; n < 16; ++n) {
            u64 e2 = es2[n * 50 + dp + 1];
            u64 t0 = f2relu(f2add(a0.y, e2));
            acc0[n] = f2fma(t0, t0, acc0[n]);
            u64 t1 = f2relu(f2add(a1.y, e2));
            acc1[n] = f2fma(t1, t1, acc1[n]);
        }
        a0 = na0; a1 = na1;
    }

    if (l0 < LL) {
#pragma unroll
        for (int n = 0; n < 16; ++n) {
            float2 v = funpack(acc0[n]);
            out[(size_t)(n0 + n) * LL + l0] = -fsqrt_ap(v.x + v.y);
        }
    }
    if (l1 < LL) {
#pragma unroll
        for (int n = 0; n < 16; ++n) {
            float2 v = funpack(acc1[n]);
            out[(size_t)(n0 + n) * LL + l1] = -fsqrt_ap(v.x + v.y);
        }
    }
}

// ---------------------------------------------------------------------------
extern "C" void kernel_launch(void* const* d_in, const int* in_sizes, int n_in,
                              void* d_out, int out_size)
{
    const float* vfs = (const float*)d_in[0];   // [256, 4096]
    const float* lv  = (const float*)d_in[1];   // [20000, 100]
    const float* W1  = (const float*)d_in[2];   // [4096, 1024]
    const float* b1  = (const float*)d_in[3];   // [1024]
    const float* W2  = (const float*)d_in[4];   // [1024, 100]
    const float* b2  = (const float*)d_in[5];   // [100]
    float* out = (float*)d_out;                 // [256, 20000]

    gemm1_kernel<<<dim3(16, 4, 2), 256>>>(vfs, W1);
    gemm2_kernel<<<dim3(16, 8), 256>>>(W2, b1);
    score_kernel<<<dim3(40, 16), 256>>>(lv, b2, out);
}